// round 3
// baseline (speedup 1.0000x reference)
#include <cuda_runtime.h>
#include <cuda_bf16.h>
#include <cstdint>

// Problem constants (shapes fixed by the dataset)
#define N_NODES_MAX 100096          // padded
#define F 128                       // F_IN == CONV_H == 128
#define LIN_H 64
#define N_CLASSES 10
#define NUM_GRAPHS 64

// ---------------- scratch (device globals; no allocation allowed) ----------
__device__ float        g_deg[N_NODES_MAX];
__device__ float        g_dinv[N_NODES_MAX];
__device__ float        g_agg[(size_t)N_NODES_MAX * F];      // ~51 MB
__device__ unsigned int g_pool[NUM_GRAPHS * F];              // float-as-uint max
__device__ float        g_t1[NUM_GRAPHS * LIN_H];

// ---------------- kernel 1: zero scratch -----------------------------------
__global__ void zero_kernel(int n4, int n) {
    int idx = blockIdx.x * blockDim.x + threadIdx.x;
    if (idx < n4) {
        ((float4*)g_agg)[idx] = make_float4(0.f, 0.f, 0.f, 0.f);
    }
    if (idx < n)               g_deg[idx]  = 0.f;
    if (idx < NUM_GRAPHS * F)  g_pool[idx] = 0u;   // 0u == 0.0f bits; relu>=0 so safe
}

// ---------------- kernel 2: weighted in-degree ------------------------------
__global__ void deg_kernel(const int* __restrict__ ei, const float* __restrict__ ew, int E) {
    int e = blockIdx.x * blockDim.x + threadIdx.x;
    if (e >= E) return;
    int c = ei[E + e];                 // edge_index[1][e] = target
    atomicAdd(&g_deg[c], ew[e]);
}

// ---------------- kernel 3: dinv = rsqrt(deg + selfloop) --------------------
__global__ void dinv_kernel(int n) {
    int i = blockIdx.x * blockDim.x + threadIdx.x;
    if (i >= n) return;
    g_dinv[i] = rsqrtf(g_deg[i] + 1.0f);   // self-loop weight 1 => deg>0 always
}

// ---------------- kernel 4: edge scatter (one warp per edge) ----------------
__global__ void scatter_kernel(const float* __restrict__ x,
                               const int* __restrict__ ei,
                               const float* __restrict__ ew, int E) {
    int warp = (blockIdx.x * blockDim.x + threadIdx.x) >> 5;
    int lane = threadIdx.x & 31;
    if (warp >= E) return;
    int r = ei[warp];          // source
    int c = ei[E + warp];      // target
    float coef = g_dinv[r] * ew[warp] * g_dinv[c];
    float4 v = ((const float4*)x)[(size_t)r * 32 + lane];   // 512B coalesced gather
    float* dst = g_agg + (size_t)c * F + lane * 4;
    asm volatile("red.global.add.v4.f32 [%0], {%1, %2, %3, %4};"
                 :: "l"(dst), "f"(coef * v.x), "f"(coef * v.y),
                    "f"(coef * v.z), "f"(coef * v.w)
                 : "memory");
}

// ---------------- kernel 5: fused (agg + dinv^2 x) @ W + b, relu, pool-max --
// 128 rows x 128 cols per block, 256 threads, 8x8 microtile.
#define AS_LD 130   // pad: bank-conflict-free column reads
__global__ __launch_bounds__(256) void gemm_pool_kernel(
        const float* __restrict__ x,
        const float* __restrict__ w,       // [128,128] k-major rows
        const float* __restrict__ bias,    // [128]
        const int*   __restrict__ batch,
        int n) {
    extern __shared__ float sm[];
    float* As = sm;                 // 128*130
    float* Bs = sm + 128 * AS_LD;   // 128*128

    int tid  = threadIdx.x;
    int row0 = blockIdx.x * 128;

    // load W tile (exact layout: Bs[k][j] = w[k*128+j])
    {
        const float4* w4 = (const float4*)w;
        float4* b4 = (float4*)Bs;
        #pragma unroll
        for (int i = tid; i < 4096; i += 256) b4[i] = w4[i];
    }
    // load A tile fused with self-loop: As[row][k] = agg + dinv^2 * x
    {
        const float4* agg4 = (const float4*)g_agg;
        const float4* x4   = (const float4*)x;
        #pragma unroll
        for (int i = tid; i < 4096; i += 256) {
            int rr = i >> 5, kq = i & 31;
            int gr = row0 + rr;
            float4 v = make_float4(0.f, 0.f, 0.f, 0.f);
            if (gr < n) {
                float4 a  = agg4[(size_t)gr * 32 + kq];
                float4 xv = x4[(size_t)gr * 32 + kq];
                float d = g_dinv[gr];
                float d2 = d * d;
                v.x = a.x + d2 * xv.x;  v.y = a.y + d2 * xv.y;
                v.z = a.z + d2 * xv.z;  v.w = a.w + d2 * xv.w;
            }
            float* p = As + rr * AS_LD + kq * 4;
            p[0] = v.x; p[1] = v.y; p[2] = v.z; p[3] = v.w;
        }
    }
    __syncthreads();

    int ty = tid >> 4, tx = tid & 15;
    int r0 = ty * 8, c0 = tx * 8;
    float acc[8][8];
    #pragma unroll
    for (int i = 0; i < 8; i++)
        #pragma unroll
        for (int j = 0; j < 8; j++) acc[i][j] = 0.f;

    const float4* Bs4 = (const float4*)Bs;
    #pragma unroll 4
    for (int k = 0; k < 128; k++) {
        float a[8];
        #pragma unroll
        for (int i = 0; i < 8; i++) a[i] = As[(r0 + i) * AS_LD + k];
        float4 b0 = Bs4[k * 32 + tx * 2];
        float4 b1 = Bs4[k * 32 + tx * 2 + 1];
        float b[8] = {b0.x, b0.y, b0.z, b0.w, b1.x, b1.y, b1.z, b1.w};
        #pragma unroll
        for (int i = 0; i < 8; i++)
            #pragma unroll
            for (int j = 0; j < 8; j++) acc[i][j] += a[i] * b[j];
    }

    // epilogue: bias + relu + per-graph max, segment-aware (batch sorted)
    float bb[8];
    #pragma unroll
    for (int j = 0; j < 8; j++) bb[j] = bias[c0 + j];

    int prevg = -1;
    float m[8];
    #pragma unroll
    for (int j = 0; j < 8; j++) m[j] = 0.f;

    for (int i = 0; i < 8; i++) {
        int gr = row0 + r0 + i;
        if (gr >= n) break;
        int g = batch[gr];
        if (g != prevg) {
            if (prevg >= 0) {
                #pragma unroll
                for (int j = 0; j < 8; j++)
                    atomicMax(&g_pool[prevg * F + c0 + j], __float_as_uint(m[j]));
            }
            prevg = g;
            #pragma unroll
            for (int j = 0; j < 8; j++) m[j] = fmaxf(acc[i][j] + bb[j], 0.f);
        } else {
            #pragma unroll
            for (int j = 0; j < 8; j++) m[j] = fmaxf(m[j], fmaxf(acc[i][j] + bb[j], 0.f));
        }
    }
    if (prevg >= 0) {
        #pragma unroll
        for (int j = 0; j < 8; j++)
            atomicMax(&g_pool[prevg * F + c0 + j], __float_as_uint(m[j]));
    }
}

// ---------------- kernel 6: t1 = relu(pooled @ lin1_w + b1) -----------------
__global__ void mlp1_kernel(const float* __restrict__ w1, const float* __restrict__ b1) {
    int idx = blockIdx.x * blockDim.x + threadIdx.x;   // < 64*64
    if (idx >= NUM_GRAPHS * LIN_H) return;
    int g = idx >> 6, j = idx & 63;
    float s = b1[j];
    #pragma unroll 8
    for (int k = 0; k < F; k++)
        s += __uint_as_float(g_pool[g * F + k]) * w1[k * LIN_H + j];
    g_t1[idx] = fmaxf(s, 0.f);
}

// ---------------- kernel 7: out = t1 @ lin2_w + b2 --------------------------
__global__ void mlp2_kernel(const float* __restrict__ w2, const float* __restrict__ b2,
                            float* __restrict__ out) {
    int idx = blockIdx.x * blockDim.x + threadIdx.x;   // < 64*10
    if (idx >= NUM_GRAPHS * N_CLASSES) return;
    int g = idx / N_CLASSES, c = idx % N_CLASSES;
    float s = b2[c];
    #pragma unroll 8
    for (int j = 0; j < LIN_H; j++)
        s += g_t1[g * LIN_H + j] * w2[j * N_CLASSES + c];
    out[idx] = s;
}

// ---------------- launch ----------------------------------------------------
extern "C" void kernel_launch(void* const* d_in, const int* in_sizes, int n_in,
                              void* d_out, int out_size) {
    const float* x      = (const float*)d_in[0];
    const int*   ei     = (const int*)d_in[1];   // [2,E] row-major, assumed int32
    const float* ew     = (const float*)d_in[2];
    const int*   batch  = (const int*)d_in[3];   // assumed int32, sorted
    const float* conv_w = (const float*)d_in[4];
    const float* conv_b = (const float*)d_in[5];
    const float* lin1_w = (const float*)d_in[6];
    const float* lin1_b = (const float*)d_in[7];
    const float* lin2_w = (const float*)d_in[8];
    const float* lin2_b = (const float*)d_in[9];
    float* out = (float*)d_out;

    int E = in_sizes[2];          // n_edges from edge_weight
    int n = in_sizes[3];          // n_nodes from batch

    const int smem_gemm = (128 * AS_LD + 128 * 128) * (int)sizeof(float);
    cudaFuncSetAttribute(gemm_pool_kernel,
                         cudaFuncAttributeMaxDynamicSharedMemorySize, smem_gemm);

    int n4 = n * 32;                                   // float4 count of agg
    zero_kernel<<<(n4 + 255) / 256, 256>>>(n4, n);
    deg_kernel<<<(E + 255) / 256, 256>>>(ei, ew, E);
    dinv_kernel<<<(n + 255) / 256, 256>>>(n);
    scatter_kernel<<<(E + 7) / 8, 256>>>(x, ei, ew, E);
    gemm_pool_kernel<<<(n + 127) / 128, 256, smem_gemm>>>(x, conv_w, conv_b, batch, n);
    mlp1_kernel<<<(NUM_GRAPHS * LIN_H + 255) / 256, 256>>>(lin1_w, lin1_b);
    mlp2_kernel<<<(NUM_GRAPHS * N_CLASSES + 255) / 256, 256>>>(lin2_w, lin2_b, out);
}

// round 4
// speedup vs baseline: 1.4844x; 1.4844x over previous
#include <cuda_runtime.h>
#include <cuda_bf16.h>
#include <cstdint>

// Problem constants (shapes fixed by the dataset)
#define N_NODES_MAX 100096
#define E_MAX       1600000
#define F 128
#define LIN_H 64
#define N_CLASSES 10
#define NUM_GRAPHS 64
#define SCAN_B 1024

// ---------------- scratch (device globals; no allocation allowed) ----------
__device__ float        g_deg[N_NODES_MAX];
__device__ int          g_cnt[N_NODES_MAX];
__device__ int          g_start[N_NODES_MAX];
__device__ int          g_cursor[N_NODES_MAX];
__device__ int          g_bsum[256];
__device__ float        g_dinv[N_NODES_MAX];
__device__ float2       g_csr[E_MAX];                         // (src as int bits, coef)
__device__ float        g_agg[(size_t)N_NODES_MAX * F];       // ~51 MB
__device__ unsigned int g_pool[NUM_GRAPHS * F];               // float-as-uint max
__device__ float        g_t1[NUM_GRAPHS * LIN_H];

// ---------------- K1: zero small scratch ------------------------------------
__global__ void zero_kernel(int n) {
    int i = blockIdx.x * blockDim.x + threadIdx.x;
    if (i < n) { g_deg[i] = 0.f; g_cnt[i] = 0; }
    if (i < NUM_GRAPHS * F) g_pool[i] = 0u;   // relu output >= 0, bits-max is safe
}

// ---------------- K2: weighted in-degree + target histogram -----------------
__global__ void deg_kernel(const int* __restrict__ ei, const float* __restrict__ ew, int E) {
    int e = blockIdx.x * blockDim.x + threadIdx.x;
    if (e >= E) return;
    int c = ei[E + e];
    atomicAdd(&g_deg[c], ew[e]);
    atomicAdd(&g_cnt[c], 1);
}

// ---------------- K3: dinv = rsqrt(deg + 1) ---------------------------------
__global__ void dinv_kernel(int n) {
    int i = blockIdx.x * blockDim.x + threadIdx.x;
    if (i >= n) return;
    g_dinv[i] = rsqrtf(g_deg[i] + 1.0f);      // self-loop => deg > 0 always
}

// ---------------- S1/S2/S3: exclusive scan of counts ------------------------
__global__ __launch_bounds__(SCAN_B) void scan1_kernel(int n) {
    __shared__ int s[SCAN_B];
    int i = blockIdx.x * SCAN_B + threadIdx.x;
    int v = (i < n) ? g_cnt[i] : 0;
    s[threadIdx.x] = v;
    __syncthreads();
    for (int off = 1; off < SCAN_B; off <<= 1) {
        int t = (threadIdx.x >= off) ? s[threadIdx.x - off] : 0;
        __syncthreads();
        s[threadIdx.x] += t;
        __syncthreads();
    }
    if (i < n) g_start[i] = s[threadIdx.x] - v;     // local exclusive
    if (threadIdx.x == SCAN_B - 1) g_bsum[blockIdx.x] = s[SCAN_B - 1];
}

__global__ void scan2_kernel(int nb) {
    if (threadIdx.x == 0) {
        int acc = 0;
        for (int b = 0; b < nb; b++) { int t = g_bsum[b]; g_bsum[b] = acc; acc += t; }
    }
}

__global__ void scan3_kernel(int n) {
    int i = blockIdx.x * blockDim.x + threadIdx.x;
    if (i >= n) return;
    int v = g_start[i] + g_bsum[i / SCAN_B];
    g_start[i]  = v;
    g_cursor[i] = v;
}

// ---------------- K4: build CSR (by target) ---------------------------------
__global__ void csr_kernel(const int* __restrict__ ei, const float* __restrict__ ew, int E) {
    int e = blockIdx.x * blockDim.x + threadIdx.x;
    if (e >= E) return;
    int r = ei[e];
    int c = ei[E + e];
    float coef = g_dinv[r] * ew[e] * g_dinv[c];
    int pos = atomicAdd(&g_cursor[c], 1);
    g_csr[pos] = make_float2(__int_as_float(r), coef);
}

// ---------------- K5: pull-style gather, warp per node ----------------------
// agg[node] = dinv^2 * x[node]  +  sum_e coef_e * x[src_e]
__global__ __launch_bounds__(256) void gather_kernel(const float* __restrict__ x, int n) {
    int warp = (blockIdx.x * blockDim.x + threadIdx.x) >> 5;
    int lane = threadIdx.x & 31;
    if (warp >= n) return;

    const float4* x4 = (const float4*)x;
    int start = g_start[warp];
    int cnt   = g_cnt[warp];
    float d   = g_dinv[warp];

    float4 xv = x4[(size_t)warp * 32 + lane];
    float d2 = d * d;
    float4 acc = make_float4(d2 * xv.x, d2 * xv.y, d2 * xv.z, d2 * xv.w);
    float4 acc2 = make_float4(0.f, 0.f, 0.f, 0.f);

    const float2* cs = g_csr + start;
    int e = 0;
    for (; e + 1 < cnt; e += 2) {
        float2 a0 = cs[e];
        float2 a1 = cs[e + 1];
        int r0 = __float_as_int(a0.x);
        int r1 = __float_as_int(a1.x);
        float4 v0 = x4[(size_t)r0 * 32 + lane];
        float4 v1 = x4[(size_t)r1 * 32 + lane];
        acc.x  += a0.y * v0.x;  acc.y  += a0.y * v0.y;
        acc.z  += a0.y * v0.z;  acc.w  += a0.y * v0.w;
        acc2.x += a1.y * v1.x;  acc2.y += a1.y * v1.y;
        acc2.z += a1.y * v1.z;  acc2.w += a1.y * v1.w;
    }
    if (e < cnt) {
        float2 a0 = cs[e];
        int r0 = __float_as_int(a0.x);
        float4 v0 = x4[(size_t)r0 * 32 + lane];
        acc.x += a0.y * v0.x;  acc.y += a0.y * v0.y;
        acc.z += a0.y * v0.z;  acc.w += a0.y * v0.w;
    }
    acc.x += acc2.x; acc.y += acc2.y; acc.z += acc2.z; acc.w += acc2.w;
    ((float4*)g_agg)[(size_t)warp * 32 + lane] = acc;
}

// ---------------- K6: agg @ W + b, relu, segment-max pool -------------------
#define AS_LD 130
__global__ __launch_bounds__(256) void gemm_pool_kernel(
        const float* __restrict__ w,       // [128,128]
        const float* __restrict__ bias,    // [128]
        const int*   __restrict__ batch,
        int n) {
    extern __shared__ float sm[];
    float* As = sm;                 // 128*130
    float* Bs = sm + 128 * AS_LD;   // 128*128

    int tid  = threadIdx.x;
    int row0 = blockIdx.x * 128;

    {
        const float4* w4 = (const float4*)w;
        float4* b4 = (float4*)Bs;
        #pragma unroll
        for (int i = tid; i < 4096; i += 256) b4[i] = w4[i];
    }
    {
        const float4* agg4 = (const float4*)g_agg;
        #pragma unroll
        for (int i = tid; i < 4096; i += 256) {
            int rr = i >> 5, kq = i & 31;
            int gr = row0 + rr;
            float4 v = make_float4(0.f, 0.f, 0.f, 0.f);
            if (gr < n) v = agg4[(size_t)gr * 32 + kq];
            float* p = As + rr * AS_LD + kq * 4;
            p[0] = v.x; p[1] = v.y; p[2] = v.z; p[3] = v.w;
        }
    }
    __syncthreads();

    int ty = tid >> 4, tx = tid & 15;
    int r0 = ty * 8, c0 = tx * 8;
    float acc[8][8];
    #pragma unroll
    for (int i = 0; i < 8; i++)
        #pragma unroll
        for (int j = 0; j < 8; j++) acc[i][j] = 0.f;

    const float4* Bs4 = (const float4*)Bs;
    #pragma unroll 4
    for (int k = 0; k < 128; k++) {
        float a[8];
        #pragma unroll
        for (int i = 0; i < 8; i++) a[i] = As[(r0 + i) * AS_LD + k];
        float4 b0 = Bs4[k * 32 + tx * 2];
        float4 b1 = Bs4[k * 32 + tx * 2 + 1];
        float b[8] = {b0.x, b0.y, b0.z, b0.w, b1.x, b1.y, b1.z, b1.w};
        #pragma unroll
        for (int i = 0; i < 8; i++)
            #pragma unroll
            for (int j = 0; j < 8; j++) acc[i][j] += a[i] * b[j];
    }

    float bb[8];
    #pragma unroll
    for (int j = 0; j < 8; j++) bb[j] = bias[c0 + j];

    int prevg = -1;
    float m[8];
    #pragma unroll
    for (int j = 0; j < 8; j++) m[j] = 0.f;

    for (int i = 0; i < 8; i++) {
        int gr = row0 + r0 + i;
        if (gr >= n) break;
        int g = batch[gr];
        if (g != prevg) {
            if (prevg >= 0) {
                #pragma unroll
                for (int j = 0; j < 8; j++)
                    atomicMax(&g_pool[prevg * F + c0 + j], __float_as_uint(m[j]));
            }
            prevg = g;
            #pragma unroll
            for (int j = 0; j < 8; j++) m[j] = fmaxf(acc[i][j] + bb[j], 0.f);
        } else {
            #pragma unroll
            for (int j = 0; j < 8; j++) m[j] = fmaxf(m[j], fmaxf(acc[i][j] + bb[j], 0.f));
        }
    }
    if (prevg >= 0) {
        #pragma unroll
        for (int j = 0; j < 8; j++)
            atomicMax(&g_pool[prevg * F + c0 + j], __float_as_uint(m[j]));
    }
}

// ---------------- K7: t1 = relu(pooled @ lin1_w + b1) -----------------------
__global__ void mlp1_kernel(const float* __restrict__ w1, const float* __restrict__ b1) {
    int idx = blockIdx.x * blockDim.x + threadIdx.x;
    if (idx >= NUM_GRAPHS * LIN_H) return;
    int g = idx >> 6, j = idx & 63;
    float s = b1[j];
    #pragma unroll 8
    for (int k = 0; k < F; k++)
        s += __uint_as_float(g_pool[g * F + k]) * w1[k * LIN_H + j];
    g_t1[idx] = fmaxf(s, 0.f);
}

// ---------------- K8: out = t1 @ lin2_w + b2 --------------------------------
__global__ void mlp2_kernel(const float* __restrict__ w2, const float* __restrict__ b2,
                            float* __restrict__ out) {
    int idx = blockIdx.x * blockDim.x + threadIdx.x;
    if (idx >= NUM_GRAPHS * N_CLASSES) return;
    int g = idx / N_CLASSES, c = idx % N_CLASSES;
    float s = b2[c];
    #pragma unroll 8
    for (int j = 0; j < LIN_H; j++)
        s += g_t1[g * LIN_H + j] * w2[j * N_CLASSES + c];
    out[idx] = s;
}

// ---------------- launch ----------------------------------------------------
extern "C" void kernel_launch(void* const* d_in, const int* in_sizes, int n_in,
                              void* d_out, int out_size) {
    const float* x      = (const float*)d_in[0];
    const int*   ei     = (const int*)d_in[1];
    const float* ew     = (const float*)d_in[2];
    const int*   batch  = (const int*)d_in[3];
    const float* conv_w = (const float*)d_in[4];
    const float* conv_b = (const float*)d_in[5];
    const float* lin1_w = (const float*)d_in[6];
    const float* lin1_b = (const float*)d_in[7];
    const float* lin2_w = (const float*)d_in[8];
    const float* lin2_b = (const float*)d_in[9];
    float* out = (float*)d_out;

    int E = in_sizes[2];
    int n = in_sizes[3];
    int nscan = (n + SCAN_B - 1) / SCAN_B;

    const int smem_gemm = (128 * AS_LD + 128 * 128) * (int)sizeof(float);
    cudaFuncSetAttribute(gemm_pool_kernel,
                         cudaFuncAttributeMaxDynamicSharedMemorySize, smem_gemm);

    zero_kernel<<<(n + 255) / 256, 256>>>(n);
    deg_kernel<<<(E + 255) / 256, 256>>>(ei, ew, E);
    dinv_kernel<<<(n + 255) / 256, 256>>>(n);
    scan1_kernel<<<nscan, SCAN_B>>>(n);
    scan2_kernel<<<1, 32>>>(nscan);
    scan3_kernel<<<(n + 255) / 256, 256>>>(n);
    csr_kernel<<<(E + 255) / 256, 256>>>(ei, ew, E);
    gather_kernel<<<(n + 7) / 8, 256>>>(x, n);
    gemm_pool_kernel<<<(n + 127) / 128, 256, smem_gemm>>>(conv_w, conv_b, batch, n);
    mlp1_kernel<<<(NUM_GRAPHS * LIN_H + 255) / 256, 256>>>(lin1_w, lin1_b);
    mlp2_kernel<<<(NUM_GRAPHS * N_CLASSES + 255) / 256, 256>>>(lin2_w, lin2_b, out);
}